// round 8
// baseline (speedup 1.0000x reference)
#include <cuda_runtime.h>
#include <math.h>

#define ULL unsigned long long

// ---------------- scratch (__device__ globals: no allocation allowed) --------
__device__ float g_qc0[800];            // bq + Wq[:, :768] @ cls
__device__ float g_M[33 * 800];         // row0 = W0, rows 1..32 = gender->w_eff map
__device__ float g_weff[32 * 800];      // per-batch effective key-projection vector
__device__ float g_cst[64];             // per-batch {S1, K2}
__device__ float g_part[32 * 6 * 3 * 1024]; // per (b, e-pass): {s1,s2,sd}[token]
__device__ int   g_counter;             // dynamic task counter

// ---------------- f32x2 packed-FMA helpers (sm_100+) ------------------------
__device__ __forceinline__ void fma2(ULL &d, ULL a, ULL b) {
    asm("fma.rn.f32x2 %0, %1, %2, %0;" : "+l"(d) : "l"(a), "l"(b));
}
__device__ __forceinline__ float2 unpk(ULL v) {
    float2 f; asm("mov.b64 {%0, %1}, %2;" : "=f"(f.x), "=f"(f.y) : "l"(v)); return f;
}
// bank-decorrelating pad: insert 4 floats per 32-float block
__device__ __forceinline__ int padidx(int f) { return f + ((f >> 5) << 2); }

// ============================================================================
// prepA1: qc0[d] = bq[d] + Wq[d,:768].cls  (warp per row) + zero g_M + counter
// ============================================================================
__global__ void prepA1(const float* __restrict__ cls,
                       const float* __restrict__ qkv_w,
                       const float* __restrict__ qkv_b)
{
    const int tid = threadIdx.x;
    const int gtid = blockIdx.x * 256 + tid;
    for (int f = gtid; f < 33 * 800; f += 100 * 256) g_M[f] = 0.f;
    if (gtid == 0) g_counter = 0;

    const int d = blockIdx.x * 8 + (tid >> 5);
    const int lane = tid & 31;
    const float* wr = qkv_w + (size_t)d * 800;
    float acc = 0.f;
    for (int e = lane; e < 768; e += 32) acc = fmaf(wr[e], cls[e], acc);
    #pragma unroll
    for (int off = 16; off; off >>= 1)
        acc += __shfl_xor_sync(0xffffffffu, acc, off);
    if (lane == 0) g_qc0[d] = acc + qkv_b[d];
}

// ============================================================================
// prepA2: g_M[i][e] += sum_d u[d][i] * Wk[d][e]
// ============================================================================
__global__ void prepA2(const float* __restrict__ qkv_w)
{
    __shared__ __align__(16) float us[200 * 36];
    const int tid = threadIdx.x;
    const int e = blockIdx.x * 128 + tid;
    const int d0 = blockIdx.y * 200;

    for (int f = tid; f < 200 * 36; f += 128) {
        int dd = f / 36, i = f - dd * 36;
        float v = 0.f;
        if (i == 0)       v = g_qc0[d0 + dd];
        else if (i < 33)  v = qkv_w[(size_t)(d0 + dd) * 800 + 768 + (i - 1)];
        us[f] = v;
    }
    __syncthreads();
    if (e >= 800) return;

    float4 a[9];
    #pragma unroll
    for (int q = 0; q < 9; q++) a[q] = make_float4(0.f, 0.f, 0.f, 0.f);

    const float* wkp = qkv_w + (size_t)(800 + d0) * 800 + e;
    #pragma unroll 2
    for (int dd = 0; dd < 200; dd++) {
        float wk = wkp[(size_t)dd * 800];
        const float4* up = (const float4*)&us[dd * 36];
        #pragma unroll
        for (int q = 0; q < 9; q++) {
            float4 u = up[q];
            a[q].x = fmaf(u.x, wk, a[q].x);
            a[q].y = fmaf(u.y, wk, a[q].y);
            a[q].z = fmaf(u.z, wk, a[q].z);
            a[q].w = fmaf(u.w, wk, a[q].w);
        }
    }
    #pragma unroll
    for (int q = 0; q < 9; q++) {
        float c[4] = {a[q].x, a[q].y, a[q].z, a[q].w};
        #pragma unroll
        for (int k = 0; k < 4; k++) {
            int i = q * 4 + k;
            if (i < 33) atomicAdd(&g_M[i * 800 + e], c[k]);
        }
    }
}

// ============================================================================
// prepB: per batch — w_eff = M[0] + g@M[1:], S1, K2
// ============================================================================
__global__ void prepB(const float* __restrict__ gender,
                      const float* __restrict__ qkv_w,
                      const float* __restrict__ qkv_b,
                      const float* __restrict__ ln_g,
                      const float* __restrict__ ln_b)
{
    __shared__ float gs[32];
    __shared__ float red[24];
    const int b = blockIdx.x, tid = threadIdx.x;
    if (tid < 32) gs[tid] = gender[b * 32 + tid];
    __syncthreads();

    float ps1 = 0.f, ps2 = 0.f, pex = 0.f;
    for (int e = tid; e < 800; e += 256) {
        float wf = g_M[e];
        #pragma unroll
        for (int j = 0; j < 32; j++) wf = fmaf(gs[j], g_M[(1 + j) * 800 + e], wf);
        g_weff[b * 800 + e] = wf;
        if (e < 768) { ps1 = fmaf(ln_g[e], wf, ps1); ps2 = fmaf(ln_b[e], wf, ps2); }
        else         { pex = fmaf(gs[e - 768], wf, pex); }
    }
    for (int d = tid; d < 800; d += 256) {
        float qd = g_qc0[d];
        const float* wq = qkv_w + (size_t)d * 800 + 768;
        #pragma unroll
        for (int j = 0; j < 32; j++) qd = fmaf(wq[j], gs[j], qd);
        pex = fmaf(qd, qkv_b[800 + d], pex);
    }
    #pragma unroll
    for (int off = 16; off; off >>= 1) {
        ps1 += __shfl_xor_sync(0xffffffffu, ps1, off);
        ps2 += __shfl_xor_sync(0xffffffffu, ps2, off);
        pex += __shfl_xor_sync(0xffffffffu, pex, off);
    }
    const int w = tid >> 5;
    if ((tid & 31) == 0) { red[w] = ps1; red[8 + w] = ps2; red[16 + w] = pex; }
    __syncthreads();
    if (tid == 0) {
        float S1 = 0.f, S2 = 0.f, EX = 0.f;
        for (int i = 0; i < 8; i++) { S1 += red[i]; S2 += red[8 + i]; EX += red[16 + i]; }
        g_cst[b * 2 + 0] = S1;
        g_cst[b * 2 + 1] = S2 + EX;
    }
}

// ============================================================================
// fused: persistent dynamic-task GEMM + LN-stat fold.
//   A tile stored PRE-DUPLICATED ({a,a} f32x2 pairs) so the inner loop has
//   zero broadcast MOVs: 32 FFMA2 + 6 conflict-free LDS.128 per kk per thread.
// ============================================================================
#define ROWA 284   // 256 dup floats + pad (mult of 4)
#define ROWB 140   // 128 floats + pad (mult of 4)
#define A_BUF (16 * ROWA)
#define B_BUF (16 * ROWB)
#define SMEM_FLOATS (2 * A_BUF + 2 * B_BUF + 128 + 128 + 384)

__global__ __launch_bounds__(256, 2)
void fused_kernel(const float* __restrict__ x,
                  const float* __restrict__ W,
                  const float* __restrict__ conv_b,
                  const float* __restrict__ ln_g)
{
    extern __shared__ __align__(16) float sm[];
    float* As2  = sm;                       // 2 * A_BUF
    float* BsM  = sm + 2 * A_BUF;           // 2 * B_BUF
    float* uS   = BsM + 2 * B_BUF;          // 128
    float* cbS  = uS + 128;                 // 128
    float* redS = cbS + 128;                // 3 * 128
    __shared__ int s_task;

    const int tid = threadIdx.x;
    const int w = tid >> 5, lane = tid & 31;
    const int wm = w & 3, we = w >> 2;
    const int lm = lane >> 3, le = lane & 7;
    const int tm  = wm * 32 + lm * 8;       // 8 token rows
    const int teL = we * 64 + le * 8;       // 8 embed cols (logical)
    const int offA = padidx(2 * tm);        // 16 dup floats, contiguous after pad
    const int offB = padidx(teL);           // 8 floats, contiguous after pad
    const int rA = tid >> 5, cA = (tid & 31) * 4;         // A LDG coords
    const int eB = tid >> 2, qq = (tid & 3) * 4;          // B LDG coords
    const int stA = padidx((tid & 31) * 8);               // A dup-store base (row-local)
    const int stB = padidx(eB);                           // B store col (padded)

    while (true) {
        if (tid == 0) s_task = atomicAdd(&g_counter, 1);
        __syncthreads();
        const int task = s_task;
        if (task >= 1536) return;

        const int b  = task / 48;
        const int r_ = task - b * 48;
        const int mt = r_ / 6;
        const int ep = r_ - mt * 6;
        const int m0 = mt * 128;
        const int E0 = ep * 128;

        if (tid < 128) {
            uS[tid]  = ln_g[E0 + tid] * g_weff[b * 800 + E0 + tid];
            cbS[tid] = conv_b[E0 + tid];
        }

        const float* xb = x + (size_t)b * (1024 * 1024) + m0;
        const float* Wb = W + (size_t)E0 * 1024;

        float4 ra0, ra1, rb0, rb1;
        // ---- prologue: chunk 0 -> buf 0
        ra0 = *(const float4*)(xb + (size_t)rA * 1024 + cA);
        ra1 = *(const float4*)(xb + (size_t)(rA + 8) * 1024 + cA);
        rb0 = *(const float4*)(Wb + (size_t)eB * 1024 + qq);
        rb1 = *(const float4*)(Wb + (size_t)(eB + 64) * 1024 + qq);
        {
            float* a0 = As2 + rA * ROWA + stA;
            float* a1 = As2 + (rA + 8) * ROWA + stA;
            *(float4*)(a0)     = make_float4(ra0.x, ra0.x, ra0.y, ra0.y);
            *(float4*)(a0 + 4) = make_float4(ra0.z, ra0.z, ra0.w, ra0.w);
            *(float4*)(a1)     = make_float4(ra1.x, ra1.x, ra1.y, ra1.y);
            *(float4*)(a1 + 4) = make_float4(ra1.z, ra1.z, ra1.w, ra1.w);
            float* bb = BsM;
            bb[(qq + 0) * ROWB + stB] = rb0.x; bb[(qq + 1) * ROWB + stB] = rb0.y;
            bb[(qq + 2) * ROWB + stB] = rb0.z; bb[(qq + 3) * ROWB + stB] = rb0.w;
            const int stB2 = padidx(eB + 64);
            bb[(qq + 0) * ROWB + stB2] = rb1.x; bb[(qq + 1) * ROWB + stB2] = rb1.y;
            bb[(qq + 2) * ROWB + stB2] = rb1.z; bb[(qq + 3) * ROWB + stB2] = rb1.w;
        }
        __syncthreads();

        ULL acc[8][4];
        #pragma unroll
        for (int i = 0; i < 8; i++)
            #pragma unroll
            for (int j = 0; j < 4; j++) acc[i][j] = 0ull;

        for (int kc = 0; kc < 64; kc++) {
            const int cur = kc & 1;
            if (kc < 63) {
                const int c0 = (kc + 1) * 16;
                ra0 = *(const float4*)(xb + (size_t)(c0 + rA) * 1024 + cA);
                ra1 = *(const float4*)(xb + (size_t)(c0 + rA + 8) * 1024 + cA);
                rb0 = *(const float4*)(Wb + (size_t)eB * 1024 + c0 + qq);
                rb1 = *(const float4*)(Wb + (size_t)(eB + 64) * 1024 + c0 + qq);
            }
            const float* Asb = As2 + cur * A_BUF + offA;
            const float* Bsb = BsM + cur * B_BUF + offB;
            #pragma unroll
            for (int kk = 0; kk < 16; kk++) {
                const ULL* ap = (const ULL*)(Asb + kk * ROWA);
                const ULL* bp = (const ULL*)(Bsb + kk * ROWB);
                ULL b0 = bp[0], b1 = bp[1], b2 = bp[2], b3 = bp[3];
                #pragma unroll
                for (int i = 0; i < 8; i++) {
                    ULL a = ap[i];
                    fma2(acc[i][0], a, b0);
                    fma2(acc[i][1], a, b1);
                    fma2(acc[i][2], a, b2);
                    fma2(acc[i][3], a, b3);
                }
            }
            if (kc < 63) {
                const int nx = cur ^ 1;
                float* a0 = As2 + nx * A_BUF + rA * ROWA + stA;
                float* a1 = As2 + nx * A_BUF + (rA + 8) * ROWA + stA;
                *(float4*)(a0)     = make_float4(ra0.x, ra0.x, ra0.y, ra0.y);
                *(float4*)(a0 + 4) = make_float4(ra0.z, ra0.z, ra0.w, ra0.w);
                *(float4*)(a1)     = make_float4(ra1.x, ra1.x, ra1.y, ra1.y);
                *(float4*)(a1 + 4) = make_float4(ra1.z, ra1.z, ra1.w, ra1.w);
                float* bb = BsM + nx * B_BUF;
                bb[(qq + 0) * ROWB + stB] = rb0.x; bb[(qq + 1) * ROWB + stB] = rb0.y;
                bb[(qq + 2) * ROWB + stB] = rb0.z; bb[(qq + 3) * ROWB + stB] = rb0.w;
                const int stB2 = padidx(eB + 64);
                bb[(qq + 0) * ROWB + stB2] = rb1.x; bb[(qq + 1) * ROWB + stB2] = rb1.y;
                bb[(qq + 2) * ROWB + stB2] = rb1.z; bb[(qq + 3) * ROWB + stB2] = rb1.w;
                __syncthreads();
            }
        }

        // ---- fold this e-pass into (s1, s2, sd)
        float r1[8], r2[8], rd[8];
        #pragma unroll
        for (int i = 0; i < 8; i++) { r1[i] = 0.f; r2[i] = 0.f; rd[i] = 0.f; }
        #pragma unroll
        for (int i = 0; i < 8; i++) {
            #pragma unroll
            for (int j = 0; j < 4; j++) {
                float2 p = unpk(acc[i][j]);
                const int ee = teL + j * 2;
                float p0 = p.x + cbS[ee];
                float p1 = p.y + cbS[ee + 1];
                r1[i] += p0 + p1;
                r2[i]  = fmaf(p0, p0, fmaf(p1, p1, r2[i]));
                rd[i]  = fmaf(p0, uS[ee], fmaf(p1, uS[ee + 1], rd[i]));
            }
        }
        #pragma unroll
        for (int i = 0; i < 8; i++) {
            #pragma unroll
            for (int off = 1; off < 8; off <<= 1) {
                r1[i] += __shfl_xor_sync(0xffffffffu, r1[i], off);
                r2[i] += __shfl_xor_sync(0xffffffffu, r2[i], off);
                rd[i] += __shfl_xor_sync(0xffffffffu, rd[i], off);
            }
        }
        __syncthreads();
        if (we == 1 && le == 0) {
            #pragma unroll
            for (int i = 0; i < 8; i++) {
                redS[0 * 128 + tm + i] = r1[i];
                redS[1 * 128 + tm + i] = r2[i];
                redS[2 * 128 + tm + i] = rd[i];
            }
        }
        __syncthreads();
        if (we == 0 && le == 0) {
            const int base = ((b * 6 + ep) * 3) * 1024 + m0 + tm;
            #pragma unroll
            for (int i = 0; i < 8; i++) {
                g_part[base + i]        = r1[i] + redS[0 * 128 + tm + i];
                g_part[base + 1024 + i] = r2[i] + redS[1 * 128 + tm + i];
                g_part[base + 2048 + i] = rd[i] + redS[2 * 128 + tm + i];
            }
        }
    }
}

// ============================================================================
// final: combine e-pass partials -> score -> softmax -> out (B,1,32,32)
// ============================================================================
__global__ void final_kernel(float* __restrict__ out)
{
    __shared__ float sc[1024];
    __shared__ float red[8];
    const int b = blockIdx.x, tid = threadIdx.x;
    const float S1 = g_cst[b * 2 + 0];
    const float K2 = g_cst[b * 2 + 1];

    #pragma unroll
    for (int k = 0; k < 4; k++) {
        const int tk = tid + k * 256;
        float s1 = 0.f, s2 = 0.f, sd = 0.f;
        #pragma unroll
        for (int ep = 0; ep < 6; ep++) {
            const int base = ((b * 6 + ep) * 3) * 1024 + tk;
            s1 += g_part[base];
            s2 += g_part[base + 1024];
            sd += g_part[base + 2048];
        }
        float mu   = s1 * (1.0f / 768.0f);
        float var  = s2 * (1.0f / 768.0f) - mu * mu;
        float rstd = rsqrtf(var + 1e-5f);
        sc[tk] = 0.035355339059327376f * (rstd * (sd - mu * S1) + K2);
    }
    __syncthreads();

    float4 s = *(const float4*)&sc[tid * 4];
    float mx = fmaxf(fmaxf(s.x, s.y), fmaxf(s.z, s.w));
    #pragma unroll
    for (int off = 16; off; off >>= 1)
        mx = fmaxf(mx, __shfl_xor_sync(0xffffffffu, mx, off));
    if ((tid & 31) == 0) red[tid >> 5] = mx;
    __syncthreads();
    float m = red[0];
    #pragma unroll
    for (int i = 1; i < 8; i++) m = fmaxf(m, red[i]);

    float e0 = expf(s.x - m), e1 = expf(s.y - m);
    float e2 = expf(s.z - m), e3 = expf(s.w - m);
    float sum = e0 + e1 + e2 + e3;
    #pragma unroll
    for (int off = 16; off; off >>= 1)
        sum += __shfl_xor_sync(0xffffffffu, sum, off);
    __syncthreads();
    if ((tid & 31) == 0) red[tid >> 5] = sum;
    __syncthreads();
    float tot = 0.f;
    #pragma unroll
    for (int i = 0; i < 8; i++) tot += red[i];
    float inv = 1.0f / tot;

    float4 o = make_float4(e0 * inv, e1 * inv, e2 * inv, e3 * inv);
    *(float4*)&out[b * 1024 + tid * 4] = o;
}

// ============================================================================
extern "C" void kernel_launch(void* const* d_in, const int* in_sizes, int n_in,
                              void* d_out, int out_size)
{
    const float* x      = (const float*)d_in[0];  // (32,1024,32,32)
    const float* gender = (const float*)d_in[1];  // (32,32)
    const float* conv_w = (const float*)d_in[2];  // (768,1024)
    const float* conv_b = (const float*)d_in[3];  // (768)
    const float* ln_g   = (const float*)d_in[4];  // (768)
    const float* ln_b   = (const float*)d_in[5];  // (768)
    const float* cls    = (const float*)d_in[6];  // (1,1,768)
    const float* qkv_w  = (const float*)d_in[7];  // (2400,800)
    const float* qkv_b  = (const float*)d_in[8];  // (2400)

    static int smem_set = 0;
    if (!smem_set) {
        cudaFuncSetAttribute(fused_kernel,
                             cudaFuncAttributeMaxDynamicSharedMemorySize,
                             SMEM_FLOATS * 4);
        smem_set = 1;
    }

    prepA1<<<100, 256>>>(cls, qkv_w, qkv_b);
    prepA2<<<dim3(7, 4), 128>>>(qkv_w);
    prepB<<<32, 256>>>(gender, qkv_w, qkv_b, ln_g, ln_b);

    fused_kernel<<<304, 256, SMEM_FLOATS * 4>>>(x, conv_w, conv_b, ln_g);

    final_kernel<<<32, 256>>>((float*)d_out);
}

// round 11
// speedup vs baseline: 1.4238x; 1.4238x over previous
#include <cuda_runtime.h>
#include <cuda_bf16.h>
#include <math.h>
#include <stdint.h>

// ---------------- scratch (__device__ globals: no allocation allowed) --------
__device__ float g_qc0[800];
__device__ float g_M[33 * 800];
__device__ float g_weff[32 * 800];
__device__ float g_cst[64];
__device__ float g_part[32 * 6 * 3 * 1024];
__device__ int   g_counter;

// bf16-split operands
__device__ __nv_bfloat16 g_xhi[32 * 1024 * 1024];  // x transposed: [b][m][c]
__device__ __nv_bfloat16 g_xlo[32 * 1024 * 1024];
__device__ __nv_bfloat16 g_whi[768 * 1024];        // [e][c]
__device__ __nv_bfloat16 g_wlo[768 * 1024];

// ---------------- helpers ----------------------------------------------------
__device__ __forceinline__ uint32_t smem_u32(const void* p) {
    uint32_t a;
    asm("{ .reg .u64 t; cvta.to.shared.u64 t, %1; cvt.u32.u64 %0, t; }"
        : "=r"(a) : "l"(p));
    return a;
}
__device__ __forceinline__ void cp16(uint32_t dst, const void* src) {
    asm volatile("cp.async.cg.shared.global [%0], [%1], 16;"
                 :: "r"(dst), "l"(src) : "memory");
}
#define CP_COMMIT() asm volatile("cp.async.commit_group;" ::: "memory")
#define CP_WAIT(N)  asm volatile("cp.async.wait_group %0;" :: "n"(N) : "memory")

__device__ __forceinline__ void ldsm4(uint32_t* r, uint32_t addr) {
    asm volatile("ldmatrix.sync.aligned.m8n8.x4.shared.b16 {%0,%1,%2,%3}, [%4];"
                 : "=r"(r[0]), "=r"(r[1]), "=r"(r[2]), "=r"(r[3]) : "r"(addr));
}
__device__ __forceinline__ void mma16816(float* d, const uint32_t* a,
                                         uint32_t b0, uint32_t b1) {
    asm volatile(
        "mma.sync.aligned.m16n8k16.row.col.f32.bf16.bf16.f32 "
        "{%0,%1,%2,%3}, {%4,%5,%6,%7}, {%8,%9}, {%0,%1,%2,%3};"
        : "+f"(d[0]), "+f"(d[1]), "+f"(d[2]), "+f"(d[3])
        : "r"(a[0]), "r"(a[1]), "r"(a[2]), "r"(a[3]), "r"(b0), "r"(b1));
}

// ============================================================================
// prepA1: qc0[d] = bq[d] + Wq[d,:768].cls + zero g_M + reset counter
// ============================================================================
__global__ void prepA1(const float* __restrict__ cls,
                       const float* __restrict__ qkv_w,
                       const float* __restrict__ qkv_b)
{
    const int tid = threadIdx.x;
    const int gtid = blockIdx.x * 256 + tid;
    for (int f = gtid; f < 33 * 800; f += 100 * 256) g_M[f] = 0.f;
    if (gtid == 0) g_counter = 0;

    const int d = blockIdx.x * 8 + (tid >> 5);
    const int lane = tid & 31;
    const float* wr = qkv_w + (size_t)d * 800;
    float acc = 0.f;
    for (int e = lane; e < 768; e += 32) acc = fmaf(wr[e], cls[e], acc);
    #pragma unroll
    for (int off = 16; off; off >>= 1)
        acc += __shfl_xor_sync(0xffffffffu, acc, off);
    if (lane == 0) g_qc0[d] = acc + qkv_b[d];
}

// ============================================================================
// prepA2: g_M[i][e] += sum_d u[d][i] * Wk[d][e]
// ============================================================================
__global__ void prepA2(const float* __restrict__ qkv_w)
{
    __shared__ __align__(16) float us[200 * 36];
    const int tid = threadIdx.x;
    const int e = blockIdx.x * 128 + tid;
    const int d0 = blockIdx.y * 200;

    for (int f = tid; f < 200 * 36; f += 128) {
        int dd = f / 36, i = f - dd * 36;
        float v = 0.f;
        if (i == 0)       v = g_qc0[d0 + dd];
        else if (i < 33)  v = qkv_w[(size_t)(d0 + dd) * 800 + 768 + (i - 1)];
        us[f] = v;
    }
    __syncthreads();
    if (e >= 800) return;

    float4 a[9];
    #pragma unroll
    for (int q = 0; q < 9; q++) a[q] = make_float4(0.f, 0.f, 0.f, 0.f);

    const float* wkp = qkv_w + (size_t)(800 + d0) * 800 + e;
    #pragma unroll 2
    for (int dd = 0; dd < 200; dd++) {
        float wk = wkp[(size_t)dd * 800];
        const float4* up = (const float4*)&us[dd * 36];
        #pragma unroll
        for (int q = 0; q < 9; q++) {
            float4 u = up[q];
            a[q].x = fmaf(u.x, wk, a[q].x);
            a[q].y = fmaf(u.y, wk, a[q].y);
            a[q].z = fmaf(u.z, wk, a[q].z);
            a[q].w = fmaf(u.w, wk, a[q].w);
        }
    }
    #pragma unroll
    for (int q = 0; q < 9; q++) {
        float c[4] = {a[q].x, a[q].y, a[q].z, a[q].w};
        #pragma unroll
        for (int k = 0; k < 4; k++) {
            int i = q * 4 + k;
            if (i < 33) atomicAdd(&g_M[i * 800 + e], c[k]);
        }
    }
}

// ============================================================================
// prepB: per batch — w_eff = M[0] + g@M[1:], S1, K2
// ============================================================================
__global__ void prepB(const float* __restrict__ gender,
                      const float* __restrict__ qkv_w,
                      const float* __restrict__ qkv_b,
                      const float* __restrict__ ln_g,
                      const float* __restrict__ ln_b)
{
    __shared__ float gs[32];
    __shared__ float red[24];
    const int b = blockIdx.x, tid = threadIdx.x;
    if (tid < 32) gs[tid] = gender[b * 32 + tid];
    __syncthreads();

    float ps1 = 0.f, ps2 = 0.f, pex = 0.f;
    for (int e = tid; e < 800; e += 256) {
        float wf = g_M[e];
        #pragma unroll
        for (int j = 0; j < 32; j++) wf = fmaf(gs[j], g_M[(1 + j) * 800 + e], wf);
        g_weff[b * 800 + e] = wf;
        if (e < 768) { ps1 = fmaf(ln_g[e], wf, ps1); ps2 = fmaf(ln_b[e], wf, ps2); }
        else         { pex = fmaf(gs[e - 768], wf, pex); }
    }
    for (int d = tid; d < 800; d += 256) {
        float qd = g_qc0[d];
        const float* wq = qkv_w + (size_t)d * 800 + 768;
        #pragma unroll
        for (int j = 0; j < 32; j++) qd = fmaf(wq[j], gs[j], qd);
        pex = fmaf(qd, qkv_b[800 + d], pex);
    }
    #pragma unroll
    for (int off = 16; off; off >>= 1) {
        ps1 += __shfl_xor_sync(0xffffffffu, ps1, off);
        ps2 += __shfl_xor_sync(0xffffffffu, ps2, off);
        pex += __shfl_xor_sync(0xffffffffu, pex, off);
    }
    const int w = tid >> 5;
    if ((tid & 31) == 0) { red[w] = ps1; red[8 + w] = ps2; red[16 + w] = pex; }
    __syncthreads();
    if (tid == 0) {
        float S1 = 0.f, S2 = 0.f, EX = 0.f;
        for (int i = 0; i < 8; i++) { S1 += red[i]; S2 += red[8 + i]; EX += red[16 + i]; }
        g_cst[b * 2 + 0] = S1;
        g_cst[b * 2 + 1] = S2 + EX;
    }
}

// ============================================================================
// conv_w: split conv weights into bf16 hi/lo. 768 blocks x 256.
// ============================================================================
__global__ void conv_w_kernel(const float* __restrict__ W)
{
    int i = blockIdx.x * 256 + threadIdx.x;
    #pragma unroll
    for (int k = 0; k < 4; k++) {
        int idx = i + k * 196608;
        float v = W[idx];
        __nv_bfloat16 h = __float2bfloat16(v);
        float r = v - __bfloat162float(h);
        g_whi[idx] = h;
        g_wlo[idx] = __float2bfloat16(r);
    }
}

// ============================================================================
// conv_x: transpose x[b][c][m] -> x_t[b][m][c] and split into bf16 hi/lo.
// ============================================================================
__global__ void conv_x_kernel(const float* __restrict__ x)
{
    __shared__ float s[32][33];
    const int b = blockIdx.z, mt = blockIdx.x, ct = blockIdx.y;
    const int tx = threadIdx.x, ty = threadIdx.y;

    const float* xp = x + ((size_t)b * 1024 + ct * 32) * 1024 + mt * 32;
    #pragma unroll
    for (int j = 0; j < 4; j++)
        s[ty + j * 8][tx] = xp[(size_t)(ty + j * 8) * 1024 + tx];
    __syncthreads();

    const size_t ob = ((size_t)b * 1024 + mt * 32) * 1024 + ct * 32;
    #pragma unroll
    for (int j = 0; j < 4; j++) {
        int mm = ty + j * 8;
        float v = s[tx][mm];
        __nv_bfloat16 h = __float2bfloat16(v);
        float r = v - __bfloat162float(h);
        g_xhi[ob + (size_t)mm * 1024 + tx] = h;
        g_xlo[ob + (size_t)mm * 1024 + tx] = __float2bfloat16(r);
    }
}

// ============================================================================
// fused_mma: persistent mma.sync bf16 GEMM + LN-stat fold.
// Task = (b, m-tile 128, e-pass 128). K-chunk 32, cp.async double buffer.
// Tiles in smem: Ahi/Alo/Bhi/Blo, rows padded to 40 bf16 (80B) -> conflict-free
// ldmatrix. 8 warps (4m x 2n), warp tile 32x64, 3 MMA terms (hh, lh, hl).
// B is stored [n][k] k-contiguous == col-major KxN -> NON-trans ldmatrix.
// ============================================================================
#define TB 10240                 // 128 rows * 80 bytes
#define TILES_BYTES (2 * 4 * TB) // 81920

__global__ __launch_bounds__(256, 2)
void fused_mma(const float* __restrict__ conv_b, const float* __restrict__ ln_g)
{
    extern __shared__ __align__(16) char tiles[];
    __shared__ float uS[128];
    __shared__ float cbS[128];
    __shared__ float redS[3 * 128];
    __shared__ int s_task;

    const uint32_t ts = smem_u32(tiles);
    const int tid = threadIdx.x;
    const int wid = tid >> 5, lane = tid & 31;
    const int wm = wid & 3, we = wid >> 2;

    // staging coords: u = tid + 256*i -> row = u>>2, part = u&3
    const int row0 = tid >> 2, part0 = tid & 3;

    // ldmatrix per-thread offsets (within a tile)
    const uint32_t aoff = (uint32_t)((wm * 32 + (lane & 15)) * 80 + (lane >> 4) * 16);
    const int bg = lane >> 3, br = lane & 7;
    const uint32_t boff = (uint32_t)((we * 64 + ((bg >= 2) ? 8 : 0) + br) * 80 + (bg & 1) * 16);

    while (true) {
        if (tid == 0) s_task = atomicAdd(&g_counter, 1);
        __syncthreads();
        const int task = s_task;
        if (task >= 1536) return;

        const int b  = task / 48;
        const int r_ = task - b * 48;
        const int mt_ = r_ / 6;
        const int ep = r_ - mt_ * 6;
        const int m0 = mt_ * 128;
        const int E0 = ep * 128;

        if (tid < 128) {
            uS[tid]  = ln_g[E0 + tid] * g_weff[b * 800 + E0 + tid];
            cbS[tid] = conv_b[E0 + tid];
        }

        const __nv_bfloat16* srcA_h = g_xhi + (size_t)b * 1048576 + (size_t)m0 * 1024;
        const __nv_bfloat16* srcA_l = g_xlo + (size_t)b * 1048576 + (size_t)m0 * 1024;
        const __nv_bfloat16* srcB_h = g_whi + (size_t)E0 * 1024;
        const __nv_bfloat16* srcB_l = g_wlo + (size_t)E0 * 1024;

        // issue one chunk's cp.asyncs (8 x 16B per thread)
        auto issue = [&](int c, int buf) {
            const int c0 = c * 32;
            const uint32_t base = ts + (uint32_t)buf * 4 * TB;
            #pragma unroll
            for (int i = 0; i < 2; i++) {
                const int row = row0 + i * 64;
                const int part = part0;
                const size_t so = (size_t)row * 1024 + c0 + part * 8;
                const uint32_t dr = (uint32_t)(row * 80 + part * 16);
                cp16(base + 0 * TB + dr, srcA_h + so);
                cp16(base + 1 * TB + dr, srcA_l + so);
                cp16(base + 2 * TB + dr, srcB_h + so);
                cp16(base + 3 * TB + dr, srcB_l + so);
            }
            CP_COMMIT();
        };

        issue(0, 0);
        issue(1, 1);

        float acc[2][8][4];
        #pragma unroll
        for (int i = 0; i < 2; i++)
            #pragma unroll
            for (int j = 0; j < 8; j++)
                #pragma unroll
                for (int k = 0; k < 4; k++) acc[i][j][k] = 0.f;

        for (int kc = 0; kc < 32; kc++) {
            if (kc == 31) { CP_WAIT(0); } else { CP_WAIT(1); }
            __syncthreads();

            const uint32_t base = ts + (uint32_t)(kc & 1) * 4 * TB;
            const uint32_t tAh = base, tAl = base + TB;
            const uint32_t tBh = base + 2 * TB, tBl = base + 3 * TB;

            #pragma unroll
            for (int ks = 0; ks < 2; ks++) {
                const uint32_t ko = ks * 32;
                uint32_t ah[2][4], al[2][4], bb[4][4];
                #pragma unroll
                for (int mt = 0; mt < 2; mt++) {
                    ldsm4(ah[mt], tAh + aoff + mt * 1280 + ko);
                    ldsm4(al[mt], tAl + aoff + mt * 1280 + ko);
                }
                // B hi: hh + lh   (non-trans: [n][k] storage is col-major KxN)
                #pragma unroll
                for (int p = 0; p < 4; p++)
                    ldsm4(bb[p], tBh + boff + p * 1280 + ko);
                #pragma unroll
                for (int mt = 0; mt < 2; mt++)
                    #pragma unroll
                    for (int nt = 0; nt < 8; nt++) {
                        const int p = nt >> 1, o = (nt & 1) * 2;
                        mma16816(acc[mt][nt], ah[mt], bb[p][o], bb[p][o + 1]);
                        mma16816(acc[mt][nt], al[mt], bb[p][o], bb[p][o + 1]);
                    }
                // B lo: hl
                #pragma unroll
                for (int p = 0; p < 4; p++)
                    ldsm4(bb[p], tBl + boff + p * 1280 + ko);
                #pragma unroll
                for (int mt = 0; mt < 2; mt++)
                    #pragma unroll
                    for (int nt = 0; nt < 8; nt++) {
                        const int p = nt >> 1, o = (nt & 1) * 2;
                        mma16816(acc[mt][nt], ah[mt], bb[p][o], bb[p][o + 1]);
                    }
            }
            __syncthreads();
            if (kc + 2 < 32) issue(kc + 2, kc & 1);
        }

        // ---- epilogue: fold acc into (s1, s2, sd) ----
        // element (mt, nt, d): m = mt*16 + (d>=2?8:0) + (lane>>2),
        //                      eL = we*64 + nt*8 + (lane&3)*2 + (d&1)
        float rs[2][2][3];
        #pragma unroll
        for (int mt = 0; mt < 2; mt++)
            #pragma unroll
            for (int h = 0; h < 2; h++) {
                float s1 = 0.f, s2 = 0.f, sd = 0.f;
                #pragma unroll
                for (int nt = 0; nt < 8; nt++) {
                    #pragma unroll
                    for (int j = 0; j < 2; j++) {
                        const int eL = we * 64 + nt * 8 + (lane & 3) * 2 + j;
                        float p = acc[mt][nt][h * 2 + j] + cbS[eL];
                        s1 += p;
                        s2 = fmaf(p, p, s2);
                        sd = fmaf(p, uS[eL], sd);
                    }
                }
                rs[mt][h][0] = s1; rs[mt][h][1] = s2; rs[mt][h][2] = sd;
            }
        #pragma unroll
        for (int mt = 0; mt < 2; mt++)
            #pragma unroll
            for (int h = 0; h < 2; h++)
                #pragma unroll
                for (int q = 0; q < 3; q++) {
                    rs[mt][h][q] += __shfl_xor_sync(0xffffffffu, rs[mt][h][q], 1);
                    rs[mt][h][q] += __shfl_xor_sync(0xffffffffu, rs[mt][h][q], 2);
                }

        __syncthreads();
        if (we == 1 && (lane & 3) == 0) {
            #pragma unroll
            for (int mt = 0; mt < 2; mt++)
                #pragma unroll
                for (int h = 0; h < 2; h++) {
                    const int m = wm * 32 + mt * 16 + h * 8 + (lane >> 2);
                    redS[0 * 128 + m] = rs[mt][h][0];
                    redS[1 * 128 + m] = rs[mt][h][1];
                    redS[2 * 128 + m] = rs[mt][h][2];
                }
        }
        __syncthreads();
        if (we == 0 && (lane & 3) == 0) {
            const int basep = ((b * 6 + ep) * 3) * 1024 + m0;
            #pragma unroll
            for (int mt = 0; mt < 2; mt++)
                #pragma unroll
                for (int h = 0; h < 2; h++) {
                    const int m = wm * 32 + mt * 16 + h * 8 + (lane >> 2);
                    g_part[basep + m]        = rs[mt][h][0] + redS[0 * 128 + m];
                    g_part[basep + 1024 + m] = rs[mt][h][1] + redS[1 * 128 + m];
                    g_part[basep + 2048 + m] = rs[mt][h][2] + redS[2 * 128 + m];
                }
        }
    }
}

// ============================================================================
// final: combine e-pass partials -> score -> softmax -> out (B,1,32,32)
// ============================================================================
__global__ void final_kernel(float* __restrict__ out)
{
    __shared__ float sc[1024];
    __shared__ float red[8];
    const int b = blockIdx.x, tid = threadIdx.x;
    const float S1 = g_cst[b * 2 + 0];
    const float K2 = g_cst[b * 2 + 1];

    #pragma unroll
    for (int k = 0; k < 4; k++) {
        const int tk = tid + k * 256;
        float s1 = 0.f, s2 = 0.f, sd = 0.f;
        #pragma unroll
        for (int ep = 0; ep < 6; ep++) {
            const int base = ((b * 6 + ep) * 3) * 1024 + tk;
            s1 += g_part[base];
            s2 += g_part[base + 1024];
            sd += g_part[base + 2048];
        }
        float mu   = s1 * (1.0f / 768.0f);
        float var  = s2 * (1.0f / 768.0f) - mu * mu;
        float rstd = rsqrtf(var + 1e-5f);
        sc[tk] = 0.035355339059327376f * (rstd * (sd - mu * S1) + K2);
    }
    __syncthreads();

    float4 s = *(const float4*)&sc[tid * 4];
    float mx = fmaxf(fmaxf(s.x, s.y), fmaxf(s.z, s.w));
    #pragma unroll
    for (int off = 16; off; off >>= 1)
        mx = fmaxf(mx, __shfl_xor_sync(0xffffffffu, mx, off));
    if ((tid & 31) == 0) red[tid >> 5] = mx;
    __syncthreads();
    float m = red[0];
    #pragma unroll
    for (int i = 1; i < 8; i++) m = fmaxf(m, red[i]);

    float e0 = expf(s.x - m), e1 = expf(s.y - m);
    float e2 = expf(s.z - m), e3 = expf(s.w - m);
    float sum = e0 + e1 + e2 + e3;
    #pragma unroll
    for (int off = 16; off; off >>= 1)
        sum += __shfl_xor_sync(0xffffffffu, sum, off);
    __syncthreads();
    if ((tid & 31) == 0) red[tid >> 5] = sum;
    __syncthreads();
    float tot = 0.f;
    #pragma unroll
    for (int i = 0; i < 8; i++) tot += red[i];
    float inv = 1.0f / tot;

    float4 o = make_float4(e0 * inv, e1 * inv, e2 * inv, e3 * inv);
    *(float4*)&out[b * 1024 + tid * 4] = o;
}

// ============================================================================
extern "C" void kernel_launch(void* const* d_in, const int* in_sizes, int n_in,
                              void* d_out, int out_size)
{
    const float* x      = (const float*)d_in[0];  // (32,1024,32,32)
    const float* gender = (const float*)d_in[1];  // (32,32)
    const float* conv_w = (const float*)d_in[2];  // (768,1024)
    const float* conv_b = (const float*)d_in[3];  // (768)
    const float* ln_g   = (const float*)d_in[4];  // (768)
    const float* ln_b   = (const float*)d_in[5];  // (768)
    const float* cls    = (const float*)d_in[6];  // (1,1,768)
    const float* qkv_w  = (const float*)d_in[7];  // (2400,800)
    const float* qkv_b  = (const float*)d_in[8];  // (2400)

    static int smem_set = 0;
    if (!smem_set) {
        cudaFuncSetAttribute(fused_mma,
                             cudaFuncAttributeMaxDynamicSharedMemorySize,
                             TILES_BYTES);
        smem_set = 1;
    }

    conv_w_kernel<<<768, 256>>>(conv_w);
    conv_x_kernel<<<dim3(32, 32, 32), dim3(32, 8)>>>(x);

    prepA1<<<100, 256>>>(cls, qkv_w, qkv_b);
    prepA2<<<dim3(7, 4), 128>>>(qkv_w);
    prepB<<<32, 256>>>(gender, qkv_w, qkv_b, ln_g, ln_b);

    fused_mma<<<304, 256, TILES_BYTES>>>(conv_b, ln_g);

    final_kernel<<<32, 256>>>((float*)d_out);
}

// round 12
// speedup vs baseline: 2.4214x; 1.7007x over previous
#include <cuda_runtime.h>
#include <cuda_bf16.h>
#include <math.h>
#include <stdint.h>

// ---------------- scratch (__device__ globals: no allocation allowed) --------
__device__ float g_qc0[800];
__device__ float g_M[33 * 800];
__device__ float g_weff[32 * 800];
__device__ float g_cst[64];
__device__ float g_part[32 * 6 * 3 * 1024];
__device__ int   g_counter;

// bf16-split operands
__device__ __nv_bfloat16 g_xhi[32 * 1024 * 1024];  // x transposed: [b][m][c]
__device__ __nv_bfloat16 g_xlo[32 * 1024 * 1024];
__device__ __nv_bfloat16 g_whi[768 * 1024];        // [e][c]
__device__ __nv_bfloat16 g_wlo[768 * 1024];

// ---------------- helpers ----------------------------------------------------
__device__ __forceinline__ uint32_t smem_u32(const void* p) {
    uint32_t a;
    asm("{ .reg .u64 t; cvta.to.shared.u64 t, %1; cvt.u32.u64 %0, t; }"
        : "=r"(a) : "l"(p));
    return a;
}
__device__ __forceinline__ void cp16(uint32_t dst, const void* src) {
    asm volatile("cp.async.cg.shared.global [%0], [%1], 16;"
                 :: "r"(dst), "l"(src) : "memory");
}
#define CP_COMMIT() asm volatile("cp.async.commit_group;" ::: "memory")
#define CP_WAIT(N)  asm volatile("cp.async.wait_group %0;" :: "n"(N) : "memory")

__device__ __forceinline__ void ldsm4(uint32_t* r, uint32_t addr) {
    asm volatile("ldmatrix.sync.aligned.m8n8.x4.shared.b16 {%0,%1,%2,%3}, [%4];"
                 : "=r"(r[0]), "=r"(r[1]), "=r"(r[2]), "=r"(r[3]) : "r"(addr));
}
__device__ __forceinline__ void mma16816(float* d, const uint32_t* a,
                                         uint32_t b0, uint32_t b1) {
    asm volatile(
        "mma.sync.aligned.m16n8k16.row.col.f32.bf16.bf16.f32 "
        "{%0,%1,%2,%3}, {%4,%5,%6,%7}, {%8,%9}, {%0,%1,%2,%3};"
        : "+f"(d[0]), "+f"(d[1]), "+f"(d[2]), "+f"(d[3])
        : "r"(a[0]), "r"(a[1]), "r"(a[2]), "r"(a[3]), "r"(b0), "r"(b1));
}

// ============================================================================
// prepA1: qc0[d] = bq[d] + Wq[d,:768].cls + zero g_M + reset counter
// ============================================================================
__global__ void prepA1(const float* __restrict__ cls,
                       const float* __restrict__ qkv_w,
                       const float* __restrict__ qkv_b)
{
    const int tid = threadIdx.x;
    const int gtid = blockIdx.x * 256 + tid;
    for (int f = gtid; f < 33 * 800; f += 100 * 256) g_M[f] = 0.f;
    if (gtid == 0) g_counter = 0;

    const int d = blockIdx.x * 8 + (tid >> 5);
    const int lane = tid & 31;
    const float* wr = qkv_w + (size_t)d * 800;
    float acc = 0.f;
    for (int e = lane; e < 768; e += 32) acc = fmaf(wr[e], cls[e], acc);
    #pragma unroll
    for (int off = 16; off; off >>= 1)
        acc += __shfl_xor_sync(0xffffffffu, acc, off);
    if (lane == 0) g_qc0[d] = acc + qkv_b[d];
}

// ============================================================================
// prepA2: g_M[i][e] += sum_d u[d][i] * Wk[d][e]
// d split into 32 chunks of 25 -> 224 CTAs (latency-bound loop cut 8x).
// ============================================================================
#define DCH 25
__global__ void prepA2(const float* __restrict__ qkv_w)
{
    __shared__ __align__(16) float us[DCH * 36];
    const int tid = threadIdx.x;
    const int e = blockIdx.x * 128 + tid;
    const int d0 = blockIdx.y * DCH;

    for (int f = tid; f < DCH * 36; f += 128) {
        int dd = f / 36, i = f - dd * 36;
        float v = 0.f;
        if (i == 0)       v = g_qc0[d0 + dd];
        else if (i < 33)  v = qkv_w[(size_t)(d0 + dd) * 800 + 768 + (i - 1)];
        us[f] = v;
    }
    __syncthreads();
    if (e >= 800) return;

    float4 a[9];
    #pragma unroll
    for (int q = 0; q < 9; q++) a[q] = make_float4(0.f, 0.f, 0.f, 0.f);

    const float* wkp = qkv_w + (size_t)(800 + d0) * 800 + e;
    #pragma unroll
    for (int dd = 0; dd < DCH; dd++) {
        float wk = wkp[(size_t)dd * 800];
        const float4* up = (const float4*)&us[dd * 36];
        #pragma unroll
        for (int q = 0; q < 9; q++) {
            float4 u = up[q];
            a[q].x = fmaf(u.x, wk, a[q].x);
            a[q].y = fmaf(u.y, wk, a[q].y);
            a[q].z = fmaf(u.z, wk, a[q].z);
            a[q].w = fmaf(u.w, wk, a[q].w);
        }
    }
    #pragma unroll
    for (int q = 0; q < 9; q++) {
        float c[4] = {a[q].x, a[q].y, a[q].z, a[q].w};
        #pragma unroll
        for (int k = 0; k < 4; k++) {
            int i = q * 4 + k;
            if (i < 33) atomicAdd(&g_M[i * 800 + e], c[k]);
        }
    }
}

// ============================================================================
// prepB: per batch — w_eff = M[0] + g@M[1:], S1, K2
// ============================================================================
__global__ void prepB(const float* __restrict__ gender,
                      const float* __restrict__ qkv_w,
                      const float* __restrict__ qkv_b,
                      const float* __restrict__ ln_g,
                      const float* __restrict__ ln_b)
{
    __shared__ float gs[32];
    __shared__ float red[24];
    const int b = blockIdx.x, tid = threadIdx.x;
    if (tid < 32) gs[tid] = gender[b * 32 + tid];
    __syncthreads();

    float ps1 = 0.f, ps2 = 0.f, pex = 0.f;
    for (int e = tid; e < 800; e += 256) {
        float wf = g_M[e];
        #pragma unroll
        for (int j = 0; j < 32; j++) wf = fmaf(gs[j], g_M[(1 + j) * 800 + e], wf);
        g_weff[b * 800 + e] = wf;
        if (e < 768) { ps1 = fmaf(ln_g[e], wf, ps1); ps2 = fmaf(ln_b[e], wf, ps2); }
        else         { pex = fmaf(gs[e - 768], wf, pex); }
    }
    for (int d = tid; d < 800; d += 256) {
        float qd = g_qc0[d];
        const float* wq = qkv_w + (size_t)d * 800 + 768;
        #pragma unroll
        for (int j = 0; j < 32; j++) qd = fmaf(wq[j], gs[j], qd);
        pex = fmaf(qd, qkv_b[800 + d], pex);
    }
    #pragma unroll
    for (int off = 16; off; off >>= 1) {
        ps1 += __shfl_xor_sync(0xffffffffu, ps1, off);
        ps2 += __shfl_xor_sync(0xffffffffu, ps2, off);
        pex += __shfl_xor_sync(0xffffffffu, pex, off);
    }
    const int w = tid >> 5;
    if ((tid & 31) == 0) { red[w] = ps1; red[8 + w] = ps2; red[16 + w] = pex; }
    __syncthreads();
    if (tid == 0) {
        float S1 = 0.f, S2 = 0.f, EX = 0.f;
        for (int i = 0; i < 8; i++) { S1 += red[i]; S2 += red[8 + i]; EX += red[16 + i]; }
        g_cst[b * 2 + 0] = S1;
        g_cst[b * 2 + 1] = S2 + EX;
    }
}

// ============================================================================
// conv_w: split conv weights into bf16 hi/lo. 768 blocks x 256.
// ============================================================================
__global__ void conv_w_kernel(const float* __restrict__ W)
{
    int i = blockIdx.x * 256 + threadIdx.x;
    #pragma unroll
    for (int k = 0; k < 4; k++) {
        int idx = i + k * 196608;
        float v = W[idx];
        __nv_bfloat16 h = __float2bfloat16(v);
        float r = v - __bfloat162float(h);
        g_whi[idx] = h;
        g_wlo[idx] = __float2bfloat16(r);
    }
}

// ============================================================================
// conv_x: transpose x[b][c][m] -> x_t[b][m][c], split into bf16 hi/lo,
// writing coalesced __nv_bfloat162 pairs (128B per warp store).
// Tile: 64 c x 32 m. grid (32 m-tiles, 16 c-tiles, 32 b), 256 threads.
// ============================================================================
__global__ void conv_x_kernel(const float* __restrict__ x)
{
    __shared__ float s[32][66];   // [m][c], even pad -> aligned float2 reads
    const int b = blockIdx.z;
    const int m0 = blockIdx.x * 32;
    const int c0 = blockIdx.y * 64;
    const int tid = threadIdx.x;

    const float* xp = x + ((size_t)b * 1024 + c0) * 1024 + m0;
    #pragma unroll
    for (int i = 0; i < 8; i++) {
        int idx = tid + i * 256;          // 0..2047
        int cl = idx >> 5, ml = idx & 31;
        s[ml][cl] = xp[(size_t)cl * 1024 + ml];
    }
    __syncthreads();

    const size_t ob = ((size_t)b * 1024 + m0) * 1024 + c0;
    #pragma unroll
    for (int i = 0; i < 4; i++) {
        int idx = tid + i * 256;          // 0..1023
        int ml = idx >> 5, pc = idx & 31; // pair index: c = 2pc, 2pc+1
        float2 v = *(const float2*)&s[ml][2 * pc];
        __nv_bfloat16 h0 = __float2bfloat16(v.x);
        __nv_bfloat16 h1 = __float2bfloat16(v.y);
        __nv_bfloat16 l0 = __float2bfloat16(v.x - __bfloat162float(h0));
        __nv_bfloat16 l1 = __float2bfloat16(v.y - __bfloat162float(h1));
        __nv_bfloat162 hp; hp.x = h0; hp.y = h1;
        __nv_bfloat162 lp; lp.x = l0; lp.y = l1;
        *(__nv_bfloat162*)&g_xhi[ob + (size_t)ml * 1024 + 2 * pc] = hp;
        *(__nv_bfloat162*)&g_xlo[ob + (size_t)ml * 1024 + 2 * pc] = lp;
    }
}

// ============================================================================
// fused_mma: persistent mma.sync bf16 GEMM + LN-stat fold.
// Task = (b, m-tile 128, e-pass 128). K-chunk 32, cp.async depth-1 pipeline
// with a SINGLE __syncthreads per chunk:
//   CP_WAIT(0) -> sync -> issue(kc+1) into buf (kc+1)&1 -> compute(kc).
// (At the sync every warp finished compute kc-1, so buf (kc+1)&1 is free.)
// 8 warps (4m x 2n), warp tile 32x64, 3 MMA terms (hh, lh, hl).
// ============================================================================
#define TB 10240                 // 128 rows * 80 bytes
#define TILES_BYTES (2 * 4 * TB) // 81920

__global__ __launch_bounds__(256, 2)
void fused_mma(const float* __restrict__ conv_b, const float* __restrict__ ln_g)
{
    extern __shared__ __align__(16) char tiles[];
    __shared__ float uS[128];
    __shared__ float cbS[128];
    __shared__ float redS[3 * 128];
    __shared__ int s_task;

    const uint32_t ts = smem_u32(tiles);
    const int tid = threadIdx.x;
    const int wid = tid >> 5, lane = tid & 31;
    const int wm = wid & 3, we = wid >> 2;

    const int row0 = tid >> 2, part0 = tid & 3;

    const uint32_t aoff = (uint32_t)((wm * 32 + (lane & 15)) * 80 + (lane >> 4) * 16);
    const int bg = lane >> 3, br = lane & 7;
    const uint32_t boff = (uint32_t)((we * 64 + ((bg >= 2) ? 8 : 0) + br) * 80 + (bg & 1) * 16);

    while (true) {
        if (tid == 0) s_task = atomicAdd(&g_counter, 1);
        __syncthreads();
        const int task = s_task;
        if (task >= 1536) return;

        const int b  = task / 48;
        const int r_ = task - b * 48;
        const int mt_ = r_ / 6;
        const int ep = r_ - mt_ * 6;
        const int m0 = mt_ * 128;
        const int E0 = ep * 128;

        if (tid < 128) {
            uS[tid]  = ln_g[E0 + tid] * g_weff[b * 800 + E0 + tid];
            cbS[tid] = conv_b[E0 + tid];
        }

        const __nv_bfloat16* srcA_h = g_xhi + (size_t)b * 1048576 + (size_t)m0 * 1024;
        const __nv_bfloat16* srcA_l = g_xlo + (size_t)b * 1048576 + (size_t)m0 * 1024;
        const __nv_bfloat16* srcB_h = g_whi + (size_t)E0 * 1024;
        const __nv_bfloat16* srcB_l = g_wlo + (size_t)E0 * 1024;

        auto issue = [&](int c, int buf) {
            const int c0 = c * 32;
            const uint32_t base = ts + (uint32_t)buf * 4 * TB;
            #pragma unroll
            for (int i = 0; i < 2; i++) {
                const int row = row0 + i * 64;
                const size_t so = (size_t)row * 1024 + c0 + part0 * 8;
                const uint32_t dr = (uint32_t)(row * 80 + part0 * 16);
                cp16(base + 0 * TB + dr, srcA_h + so);
                cp16(base + 1 * TB + dr, srcA_l + so);
                cp16(base + 2 * TB + dr, srcB_h + so);
                cp16(base + 3 * TB + dr, srcB_l + so);
            }
            CP_COMMIT();
        };

        issue(0, 0);

        float acc[2][8][4];
        #pragma unroll
        for (int i = 0; i < 2; i++)
            #pragma unroll
            for (int j = 0; j < 8; j++)
                #pragma unroll
                for (int k = 0; k < 4; k++) acc[i][j][k] = 0.f;

        for (int kc = 0; kc < 32; kc++) {
            CP_WAIT(0);
            __syncthreads();
            if (kc < 31) issue(kc + 1, (kc + 1) & 1);

            const uint32_t base = ts + (uint32_t)(kc & 1) * 4 * TB;
            const uint32_t tAh = base, tAl = base + TB;
            const uint32_t tBh = base + 2 * TB, tBl = base + 3 * TB;

            #pragma unroll
            for (int ks = 0; ks < 2; ks++) {
                const uint32_t ko = ks * 32;
                uint32_t ah[2][4], al[2][4], bb[4][4];
                #pragma unroll
                for (int mt = 0; mt < 2; mt++) {
                    ldsm4(ah[mt], tAh + aoff + mt * 1280 + ko);
                    ldsm4(al[mt], tAl + aoff + mt * 1280 + ko);
                }
                // B hi: hh + lh   (non-trans: [n][k] storage is col-major KxN)
                #pragma unroll
                for (int p = 0; p < 4; p++)
                    ldsm4(bb[p], tBh + boff + p * 1280 + ko);
                #pragma unroll
                for (int mt = 0; mt < 2; mt++)
                    #pragma unroll
                    for (int nt = 0; nt < 8; nt++) {
                        const int p = nt >> 1, o = (nt & 1) * 2;
                        mma16816(acc[mt][nt], ah[mt], bb[p][o], bb[p][o + 1]);
                        mma16816(acc[mt][nt], al[mt], bb[p][o], bb[p][o + 1]);
                    }
                // B lo: hl
                #pragma unroll
                for (int p = 0; p < 4; p++)
                    ldsm4(bb[p], tBl + boff + p * 1280 + ko);
                #pragma unroll
                for (int mt = 0; mt < 2; mt++)
                    #pragma unroll
                    for (int nt = 0; nt < 8; nt++) {
                        const int p = nt >> 1, o = (nt & 1) * 2;
                        mma16816(acc[mt][nt], ah[mt], bb[p][o], bb[p][o + 1]);
                    }
            }
        }

        // ---- epilogue: fold acc into (s1, s2, sd) ----
        float rs[2][2][3];
        #pragma unroll
        for (int mt = 0; mt < 2; mt++)
            #pragma unroll
            for (int h = 0; h < 2; h++) {
                float s1 = 0.f, s2 = 0.f, sd = 0.f;
                #pragma unroll
                for (int nt = 0; nt < 8; nt++) {
                    #pragma unroll
                    for (int j = 0; j < 2; j++) {
                        const int eL = we * 64 + nt * 8 + (lane & 3) * 2 + j;
                        float p = acc[mt][nt][h * 2 + j] + cbS[eL];
                        s1 += p;
                        s2 = fmaf(p, p, s2);
                        sd = fmaf(p, uS[eL], sd);
                    }
                }
                rs[mt][h][0] = s1; rs[mt][h][1] = s2; rs[mt][h][2] = sd;
            }
        #pragma unroll
        for (int mt = 0; mt < 2; mt++)
            #pragma unroll
            for (int h = 0; h < 2; h++)
                #pragma unroll
                for (int q = 0; q < 3; q++) {
                    rs[mt][h][q] += __shfl_xor_sync(0xffffffffu, rs[mt][h][q], 1);
                    rs[mt][h][q] += __shfl_xor_sync(0xffffffffu, rs[mt][h][q], 2);
                }

        __syncthreads();
        if (we == 1 && (lane & 3) == 0) {
            #pragma unroll
            for (int mt = 0; mt < 2; mt++)
                #pragma unroll
                for (int h = 0; h < 2; h++) {
                    const int m = wm * 32 + mt * 16 + h * 8 + (lane >> 2);
                    redS[0 * 128 + m] = rs[mt][h][0];
                    redS[1 * 128 + m] = rs[mt][h][1];
                    redS[2 * 128 + m] = rs[mt][h][2];
                }
        }
        __syncthreads();
        if (we == 0 && (lane & 3) == 0) {
            const int basep = ((b * 6 + ep) * 3) * 1024 + m0;
            #pragma unroll
            for (int mt = 0; mt < 2; mt++)
                #pragma unroll
                for (int h = 0; h < 2; h++) {
                    const int m = wm * 32 + mt * 16 + h * 8 + (lane >> 2);
                    g_part[basep + m]        = rs[mt][h][0] + redS[0 * 128 + m];
                    g_part[basep + 1024 + m] = rs[mt][h][1] + redS[1 * 128 + m];
                    g_part[basep + 2048 + m] = rs[mt][h][2] + redS[2 * 128 + m];
                }
        }
    }
}

// ============================================================================
// final: combine e-pass partials -> score -> softmax -> out (B,1,32,32)
// ============================================================================
__global__ void final_kernel(float* __restrict__ out)
{
    __shared__ float sc[1024];
    __shared__ float red[8];
    const int b = blockIdx.x, tid = threadIdx.x;
    const float S1 = g_cst[b * 2 + 0];
    const float K2 = g_cst[b * 2 + 1];

    #pragma unroll
    for (int k = 0; k < 4; k++) {
        const int tk = tid + k * 256;
        float s1 = 0.f, s2 = 0.f, sd = 0.f;
        #pragma unroll
        for (int ep = 0; ep < 6; ep++) {
            const int base = ((b * 6 + ep) * 3) * 1024 + tk;
            s1 += g_part[base];
            s2 += g_part[base + 1024];
            sd += g_part[base + 2048];
        }
        float mu   = s1 * (1.0f / 768.0f);
        float var  = s2 * (1.0f / 768.0f) - mu * mu;
        float rstd = rsqrtf(var + 1e-5f);
        sc[tk] = 0.035355339059327376f * (rstd * (sd - mu * S1) + K2);
    }
    __syncthreads();

    float4 s = *(const float4*)&sc[tid * 4];
    float mx = fmaxf(fmaxf(s.x, s.y), fmaxf(s.z, s.w));
    #pragma unroll
    for (int off = 16; off; off >>= 1)
        mx = fmaxf(mx, __shfl_xor_sync(0xffffffffu, mx, off));
    if ((tid & 31) == 0) red[tid >> 5] = mx;
    __syncthreads();
    float m = red[0];
    #pragma unroll
    for (int i = 1; i < 8; i++) m = fmaxf(m, red[i]);

    float e0 = expf(s.x - m), e1 = expf(s.y - m);
    float e2 = expf(s.z - m), e3 = expf(s.w - m);
    float sum = e0 + e1 + e2 + e3;
    #pragma unroll
    for (int off = 16; off; off >>= 1)
        sum += __shfl_xor_sync(0xffffffffu, sum, off);
    __syncthreads();
    if ((tid & 31) == 0) red[tid >> 5] = sum;
    __syncthreads();
    float tot = 0.f;
    #pragma unroll
    for (int i = 0; i < 8; i++) tot += red[i];
    float inv = 1.0f / tot;

    float4 o = make_float4(e0 * inv, e1 * inv, e2 * inv, e3 * inv);
    *(float4*)&out[b * 1024 + tid * 4] = o;
}

// ============================================================================
extern "C" void kernel_launch(void* const* d_in, const int* in_sizes, int n_in,
                              void* d_out, int out_size)
{
    const float* x      = (const float*)d_in[0];  // (32,1024,32,32)
    const float* gender = (const float*)d_in[1];  // (32,32)
    const float* conv_w = (const float*)d_in[2];  // (768,1024)
    const float* conv_b = (const float*)d_in[3];  // (768)
    const float* ln_g   = (const float*)d_in[4];  // (768)
    const float* ln_b   = (const float*)d_in[5];  // (768)
    const float* cls    = (const float*)d_in[6];  // (1,1,768)
    const float* qkv_w  = (const float*)d_in[7];  // (2400,800)
    const float* qkv_b  = (const float*)d_in[8];  // (2400)

    static int smem_set = 0;
    if (!smem_set) {
        cudaFuncSetAttribute(fused_mma,
                             cudaFuncAttributeMaxDynamicSharedMemorySize,
                             TILES_BYTES);
        smem_set = 1;
    }

    conv_w_kernel<<<768, 256>>>(conv_w);
    conv_x_kernel<<<dim3(32, 16, 32), 256>>>(x);

    prepA1<<<100, 256>>>(cls, qkv_w, qkv_b);
    prepA2<<<dim3(7, 32), 128>>>(qkv_w);
    prepB<<<32, 256>>>(gender, qkv_w, qkv_b, ln_g, ln_b);

    fused_mma<<<304, 256, TILES_BYTES>>>(conv_b, ln_g);

    final_kernel<<<32, 256>>>((float*)d_out);
}